// round 3
// baseline (speedup 1.0000x reference)
#include <cuda_runtime.h>

// Problem constants
#define BATCH 8
#define C_IN  64
#define H_IN  128
#define W_IN  128
#define OCH   64
#define KK    9      // 3x3 taps
#define HOUT  128
#define WOUT  128
#define PIX   (HOUT*WOUT)   // 16384 per batch

// ---------------- scratch (static device globals; no allocation) -----------
__device__ __align__(16) float g_nhwc[BATCH * H_IN * W_IN * C_IN];  // 33.5 MB
__device__ __align__(16) float g_wT[KK * C_IN * OCH];               // 147 KB, [k][c][oc]

// ---------------- Kernel A1: NCHW -> NHWC transpose ------------------------
__global__ void k_transpose(const float* __restrict__ in) {
    __shared__ float tile[32][33];
    int bh = blockIdx.z;                 // b*H + y
    int b  = bh / H_IN;
    int y  = bh % H_IN;
    int xBase = blockIdx.x * 32;
    int cBase = blockIdx.y * 32;
    int tx = threadIdx.x;                // 0..31
    int ty = threadIdx.y;                // 0..7
#pragma unroll
    for (int i = 0; i < 32; i += 8) {
        int c = cBase + ty + i;
        tile[ty + i][tx] = in[(((size_t)b * C_IN + c) * H_IN + y) * W_IN + xBase + tx];
    }
    __syncthreads();
#pragma unroll
    for (int i = 0; i < 32; i += 8) {
        int x = xBase + ty + i;
        g_nhwc[(((size_t)b * H_IN + y) * W_IN + x) * C_IN + cBase + tx] = tile[tx][ty + i];
    }
}

// ---------------- Kernel A2: weight [oc][c][k] -> wT [k][c][oc] -------------
__global__ void k_wtrans(const float* __restrict__ w) {
    int idx = blockIdx.x * 256 + threadIdx.x;
    if (idx < OCH * C_IN * KK) {
        int k  = idx % KK;
        int c  = (idx / KK) % C_IN;
        int oc = idx / (KK * C_IN);
        g_wT[(k * C_IN + c) * OCH + oc] = w[idx];
    }
}

// ---------------- Kernel B: fused deformable-sample + GEMM -----------------
// One block: output tile [64 oc][128 px] = one output row (b, ho).
// 128 threads, 8x8 microtile. K dim = 9 taps x 64 channels = 576, consumed
// as 9 taps x 4 chunks of 16 channels. Bilinear gather feeds smem Bs directly.
#define TKC 16
#define BS_STRIDE 132   // 16B-aligned float4 slots, bank-shifted rows

__global__ void __launch_bounds__(128) k_fused(const float* __restrict__ offset,
                                               const float* __restrict__ mask,
                                               const float* __restrict__ bias,
                                               float* __restrict__ out) {
    __shared__ __align__(16) float As[TKC][OCH];        // 4 KB
    __shared__ __align__(16) float Bs[TKC][BS_STRIDE];  // 8.25 KB
    __shared__ float sW[4][128];                        // premasked corner weights
    __shared__ int   sOff[4][128];                      // clamped NHWC float offsets

    int blk = blockIdx.x;
    int ho  = blk & (HOUT - 1);
    int b   = blk >> 7;
    int pBase = ho * WOUT;

    int tid = threadIdx.x;
    int tm  = tid >> 4;    // 0..7  -> oc rows tm*8..+7
    int tn  = tid & 15;    // 0..15 -> pixels tn*8..+7
    int cq  = tid & 3;     // channel quad within 16-ch chunk
    int pq  = tid >> 2;    // 0..31 pixel quad

    float acc[8][8];
#pragma unroll
    for (int i = 0; i < 8; i++)
#pragma unroll
        for (int j = 0; j < 8; j++) acc[i][j] = 0.f;

    const float* nhwcB = g_nhwc + (size_t)b * H_IN * W_IN * C_IN;
    const float* offB  = offset + (size_t)b * 2 * KK * PIX;
    const float* mskB  = mask   + (size_t)b * KK * PIX;

    for (int k = 0; k < KK; k++) {
        // ---- per-pixel bilinear params (1 pixel per thread) ----
        {
            int p  = pBase + tid;
            float py = (float)(k / 3 + ho - 1) + offB[(size_t)(2 * k) * PIX + p];
            float px = (float)(k % 3 + tid - 1) + offB[(size_t)(2 * k + 1) * PIX + p];
            float m  = mskB[(size_t)k * PIX + p];
            float y0f = floorf(py), x0f = floorf(px);
            int   y0  = (int)y0f,   x0  = (int)x0f;
            float wy1 = py - y0f, wx1 = px - x0f;
            float wy0 = 1.f - wy1, wx0 = 1.f - wx1;
#pragma unroll
            for (int c2 = 0; c2 < 4; c2++) {
                int cy = c2 >> 1, cx = c2 & 1;
                int yy = y0 + cy, xx = x0 + cx;
                bool v = (yy >= 0) & (yy < H_IN) & (xx >= 0) & (xx < W_IN);
                float w = (cy ? wy1 : wy0) * (cx ? wx1 : wx0) * m;
                sW[c2][tid]   = v ? w : 0.f;
                int yc = min(max(yy, 0), H_IN - 1);
                int xc = min(max(xx, 0), W_IN - 1);
                sOff[c2][tid] = (yc * W_IN + xc) * C_IN;
            }
        }
        __syncthreads();

        for (int c0 = 0; c0 < C_IN; c0 += TKC) {
            // ---- prefetch weight chunk into registers (issue LDGs early) ----
            float4 wreg[2];
#pragma unroll
            for (int j = 0; j < 2; j++) {
                int flat = tid + j * 128;
                int r = flat >> 4, q = flat & 15;
                wreg[j] = *(const float4*)&g_wT[(size_t)((k * C_IN) + c0 + r) * OCH + q * 4];
            }
            // ---- gather 16ch x 128px chunk: thread = 4ch x 4px ----
            float4 s[4];
            const float* basep = nhwcB + c0 + cq * 4;
#pragma unroll
            for (int i = 0; i < 4; i++) {
                int pl = pq * 4 + i;
                float4 a = make_float4(0.f, 0.f, 0.f, 0.f);
#pragma unroll
                for (int c2 = 0; c2 < 4; c2++) {
                    float w = sW[c2][pl];
                    float4 v = *(const float4*)(basep + sOff[c2][pl]);
                    a.x += w * v.x; a.y += w * v.y;
                    a.z += w * v.z; a.w += w * v.w;
                }
                s[i] = a;
            }
            // ---- commit weight chunk to smem ----
#pragma unroll
            for (int j = 0; j < 2; j++) {
                int flat = tid + j * 128;
                int r = flat >> 4, q = flat & 15;
                *(float4*)&As[r][q * 4] = wreg[j];
            }
            // 4x4 register transpose -> channel-major rows of Bs
            const float* sf = (const float*)s;
#pragma unroll
            for (int j = 0; j < 4; j++) {
                *(float4*)&Bs[cq * 4 + j][pq * 4] =
                    make_float4(sf[0 * 4 + j], sf[1 * 4 + j], sf[2 * 4 + j], sf[3 * 4 + j]);
            }
            __syncthreads();

            // ---- FMA over 16 k-steps ----
#pragma unroll
            for (int kc = 0; kc < TKC; kc++) {
                float a[8], bb[8];
                *(float4*)&a[0]  = *(float4*)&As[kc][tm * 8];
                *(float4*)&a[4]  = *(float4*)&As[kc][tm * 8 + 4];
                *(float4*)&bb[0] = *(float4*)&Bs[kc][tn * 8];
                *(float4*)&bb[4] = *(float4*)&Bs[kc][tn * 8 + 4];
#pragma unroll
                for (int i = 0; i < 8; i++)
#pragma unroll
                    for (int j = 0; j < 8; j++)
                        acc[i][j] += a[i] * bb[j];
            }
            __syncthreads();
        }
    }

    // ---- epilogue: bias + store ----
#pragma unroll
    for (int i = 0; i < 8; i++) {
        int oc   = tm * 8 + i;
        float bv = bias[oc];
        float* o = out + ((size_t)(b * OCH + oc)) * PIX + pBase + tn * 8;
        *(float4*)(o + 0) = make_float4(acc[i][0] + bv, acc[i][1] + bv,
                                        acc[i][2] + bv, acc[i][3] + bv);
        *(float4*)(o + 4) = make_float4(acc[i][4] + bv, acc[i][5] + bv,
                                        acc[i][6] + bv, acc[i][7] + bv);
    }
}

// ---------------- launch ----------------------------------------------------
extern "C" void kernel_launch(void* const* d_in, const int* in_sizes, int n_in,
                              void* d_out, int out_size) {
    const float* input  = (const float*)d_in[0];
    const float* offset = (const float*)d_in[1];
    const float* mask   = (const float*)d_in[2];
    const float* weight = (const float*)d_in[3];
    const float* bias   = (const float*)d_in[4];
    float* out = (float*)d_out;

    dim3 tb(32, 8);
    dim3 tg(W_IN / 32, C_IN / 32, BATCH * H_IN);
    k_transpose<<<tg, tb>>>(input);
    k_wtrans<<<(OCH * C_IN * KK + 255) / 256, 256>>>(weight);
    k_fused<<<BATCH * HOUT, 128>>>(offset, mask, bias, out);
}